// round 4
// baseline (speedup 1.0000x reference)
#include <cuda_runtime.h>
#include <math.h>

#define NB      1024
#define HID     128
#define DIM     16
#define NSTEPS  10

typedef unsigned long long u64;

// ---------------- device globals (no allocation allowed) ----------------
__device__ float g_y [NB*DIM];
__device__ float g_ys[NB*DIM];
__device__ float g_V [NB*DIM*DIM];   // g_V[p][dir j][comp i] = J[i][j]

// duplicated weights: each scalar stored as packed (w,w) f32x2
__device__ u64 W0d[17*HID];
__device__ u64 W1d[HID*HID];
__device__ u64 W2d[HID*HID];
__device__ u64 W3d[HID*HID];
__device__ u64 W4d[HID*DIM];

// ---------------- f32x2 helpers ----------------
__device__ __forceinline__ u64 pk2(float a, float b) {
  u64 r; asm("mov.b64 %0,{%1,%2};" : "=l"(r) : "f"(a), "f"(b)); return r;
}
__device__ __forceinline__ void upk2(u64 v, float& a, float& b) {
  asm("mov.b64 {%0,%1},%2;" : "=f"(a), "=f"(b) : "l"(v));
}
__device__ __forceinline__ void fma2(u64& d, u64 a, u64 b) {       // d += a*b
  asm("fma.rn.f32x2 %0,%1,%2,%0;" : "+l"(d) : "l"(a), "l"(b));
}
__device__ __forceinline__ u64 fma2o(u64 a, u64 b, u64 c) {        // a*b + c
  u64 d; asm("fma.rn.f32x2 %0,%1,%2,%3;" : "=l"(d) : "l"(a), "l"(b), "l"(c)); return d;
}
__device__ __forceinline__ u64 mul2(u64 a, u64 b) {
  u64 d; asm("mul.rn.f32x2 %0,%1,%2;" : "=l"(d) : "l"(a), "l"(b)); return d;
}

// ---------------- weight duplication prep ----------------
__global__ void dup_w_kernel(const float* __restrict__ W0, const float* __restrict__ W1,
                             const float* __restrict__ W2, const float* __restrict__ W3,
                             const float* __restrict__ W4)
{
  int i = blockIdx.x * blockDim.x + threadIdx.x;
  if (i < 17*HID)  W0d[i] = pk2(W0[i], W0[i]);
  if (i < HID*HID) {
    W1d[i] = pk2(W1[i], W1[i]);
    W2d[i] = pk2(W2[i], W2[i]);
    W3d[i] = pk2(W3[i], W3[i]);
  }
  if (i < HID*DIM) W4d[i] = pk2(W4[i], W4[i]);
}

// ---------------- workspace ----------------
struct WS {
  float dHT[HID][20];   // tangent activations, TRANSPOSED: [hidden k][dir r], pad 20
  float vinT[DIM][20];  // stage tangent input, [comp k][dir r]
  u64   zJS[DIM];       // (zinJ[k], zinS[k]) packed
  u64   hJS[HID];       // (hJ[k], hS[k]) packed primal hiddens
};
// sizeof = 10240 + 1280 + 128 + 1024 = 12672 bytes

// activation + scaled-tangent store (shared by layer0 and hidden layers)
__device__ __forceinline__ void act_store(WS* ws, u64 p[4], u64 t[8][4], int c0)
{
  #pragma unroll
  for (int j = 0; j < 4; ++j) {
    float aJ, aS; upk2(p[j], aJ, aS);
    float hJ = tanhf(aJ), hS = tanhf(aS);
    int col = c0 + 32*j;
    ws->hJS[col] = pk2(hJ, hS);
    float g = 1.f - hJ*hJ;
    u64 g2 = pk2(g, g);
    ulonglong2* orow = reinterpret_cast<ulonglong2*>(&ws->dHT[col][0]);
    ulonglong2 q;
    q.x = mul2(t[0][j], g2); q.y = mul2(t[1][j], g2); orow[0] = q;
    q.x = mul2(t[2][j], g2); q.y = mul2(t[3][j], g2); orow[1] = q;
    q.x = mul2(t[4][j], g2); q.y = mul2(t[5][j], g2); orow[2] = q;
    q.x = mul2(t[6][j], g2); q.y = mul2(t[7][j], g2); orow[3] = q;
  }
}

// fused hidden layer: primal (J,S) + 16-dir tangent, weights Wd, bias b
__device__ __forceinline__ void hidden_layer(WS* ws, const u64* __restrict__ Wd,
                                             const float* __restrict__ b, int c0)
{
  u64 t[8][4];
  #pragma unroll
  for (int rp = 0; rp < 8; ++rp)
    #pragma unroll
    for (int j = 0; j < 4; ++j) t[rp][j] = 0ULL;
  u64 p[4];
  #pragma unroll
  for (int j = 0; j < 4; ++j) { float bb = b[c0 + 32*j]; p[j] = pk2(bb, bb); }

  #pragma unroll 1
  for (int kg = 0; kg < 32; ++kg) {
    #pragma unroll
    for (int kk = 0; kk < 4; ++kk) {
      int k = kg*4 + kk;
      const ulonglong2* row = reinterpret_cast<const ulonglong2*>(&ws->dHT[k][0]);
      ulonglong2 q0 = row[0], q1 = row[1], q2 = row[2], q3 = row[3];
      u64 hjs = ws->hJS[k];
      const u64* wr = Wd + k*HID + c0;
      u64 w0 = wr[0], w1 = wr[32], w2 = wr[64], w3 = wr[96];
      fma2(p[0], hjs, w0); fma2(p[1], hjs, w1); fma2(p[2], hjs, w2); fma2(p[3], hjs, w3);
      fma2(t[0][0], q0.x, w0); fma2(t[1][0], q0.y, w0); fma2(t[2][0], q1.x, w0); fma2(t[3][0], q1.y, w0);
      fma2(t[4][0], q2.x, w0); fma2(t[5][0], q2.y, w0); fma2(t[6][0], q3.x, w0); fma2(t[7][0], q3.y, w0);
      fma2(t[0][1], q0.x, w1); fma2(t[1][1], q0.y, w1); fma2(t[2][1], q1.x, w1); fma2(t[3][1], q1.y, w1);
      fma2(t[4][1], q2.x, w1); fma2(t[5][1], q2.y, w1); fma2(t[6][1], q3.x, w1); fma2(t[7][1], q3.y, w1);
      fma2(t[0][2], q0.x, w2); fma2(t[1][2], q0.y, w2); fma2(t[2][2], q1.x, w2); fma2(t[3][2], q1.y, w2);
      fma2(t[4][2], q2.x, w2); fma2(t[5][2], q2.y, w2); fma2(t[6][2], q3.x, w2); fma2(t[7][2], q3.y, w2);
      fma2(t[0][3], q0.x, w3); fma2(t[1][3], q0.y, w3); fma2(t[2][3], q1.x, w3); fma2(t[3][3], q1.y, w3);
      fma2(t[4][3], q2.x, w3); fma2(t[5][3], q2.y, w3); fma2(t[6][3], q3.x, w3); fma2(t[7][3], q3.y, w3);
    }
  }
  __syncwarp();           // all lanes done reading dHT/hJS before overwrite
  act_store(ws, p, t, c0);
  __syncwarp();
}

__global__ __launch_bounds__(256)
void flow_jac_kernel(const float* __restrict__ x,  const float* __restrict__ xs,
                     const float* __restrict__ b0, const float* __restrict__ b1,
                     const float* __restrict__ b2, const float* __restrict__ b3,
                     const float* __restrict__ b4)
{
  extern __shared__ unsigned char smem_raw[];
  const int warp = threadIdx.x >> 5;
  const int lane = threadIdx.x & 31;
  WS* ws = reinterpret_cast<WS*>(smem_raw) + warp;
  const int p = blockIdx.x * 8 + warp;     // 128 blocks * 8 warps = 1024

  const int c0 = lane;
  const int d  = lane & 15;                // component owned by this lane (dup across halves)
  const int k0 = (lane >> 4) * 64;         // split-k half for output layer

  // persistent per-lane register state (lanes 0-15 authoritative, 16-31 mirrored)
  u64 z2   = pk2(x[p*DIM + d], xs[p*DIM + d]);   // (zJ, zS)
  u64 v2[8];                                      // (J[d][2rp], J[d][2rp+1]) i.e. dirs at comp d
  #pragma unroll
  for (int rp = 0; rp < 8; ++rp)
    v2[rp] = pk2((2*rp   == d) ? 1.f : 0.f,
                 (2*rp+1 == d) ? 1.f : 0.f);
  u64 u2[8]; u64 kst2 = 0ULL;
  #pragma unroll
  for (int rp = 0; rp < 8; ++rp) u2[rp] = 0ULL;

  const float dt = 1.f / NSTEPS;
  const u64 fp = pk2(dt/6.f, dt/6.f);

  for (int step = 0; step < NSTEPS; ++step) {
    const float t0 = step * dt;
    u64 ksum2 = 0ULL, usum2[8];
    #pragma unroll
    for (int rp = 0; rp < 8; ++rp) usum2[rp] = 0ULL;

    for (int s = 0; s < 4; ++s) {
      const float cs  = (s == 0) ? 0.f : ((s == 3) ? dt : 0.5f * dt);
      const float ts  = t0 + cs;
      const float wgt = (s == 0 || s == 3) ? 1.f : 2.f;
      const u64 csp  = pk2(cs, cs);
      const u64 wgtp = pk2(wgt, wgt);

      // ---- stage inputs (registers -> smem broadcast arrays) ----
      u64 vin[8];
      #pragma unroll
      for (int rp = 0; rp < 8; ++rp) vin[rp] = fma2o(u2[rp], csp, v2[rp]);
      u64 zin2 = fma2o(kst2, csp, z2);
      if (lane < 16) {
        ws->zJS[d] = zin2;
        ulonglong2* vr = reinterpret_cast<ulonglong2*>(&ws->vinT[d][0]);
        ulonglong2 q;
        q.x = vin[0]; q.y = vin[1]; vr[0] = q;
        q.x = vin[2]; q.y = vin[3]; vr[1] = q;
        q.x = vin[4]; q.y = vin[5]; vr[2] = q;
        q.x = vin[6]; q.y = vin[7]; vr[3] = q;
      }
      __syncwarp();

      // ================= layer 0 (fused primal+tangent, k=0..15 plus t row) ====
      {
        u64 t[8][4];
        #pragma unroll
        for (int rp = 0; rp < 8; ++rp)
          #pragma unroll
          for (int j = 0; j < 4; ++j) t[rp][j] = 0ULL;
        u64 pacc[4];
        #pragma unroll
        for (int j = 0; j < 4; ++j) { float bb = b0[c0 + 32*j]; pacc[j] = pk2(bb, bb); }

        #pragma unroll 1
        for (int kg = 0; kg < 4; ++kg) {
          #pragma unroll
          for (int kk = 0; kk < 4; ++kk) {
            int k = kg*4 + kk;
            const ulonglong2* row = reinterpret_cast<const ulonglong2*>(&ws->vinT[k][0]);
            ulonglong2 q0 = row[0], q1 = row[1], q2 = row[2], q3 = row[3];
            u64 zz = ws->zJS[k];
            const u64* wr = W0d + k*HID + c0;
            u64 w0 = wr[0], w1 = wr[32], w2 = wr[64], w3 = wr[96];
            fma2(pacc[0], zz, w0); fma2(pacc[1], zz, w1); fma2(pacc[2], zz, w2); fma2(pacc[3], zz, w3);
            fma2(t[0][0], q0.x, w0); fma2(t[1][0], q0.y, w0); fma2(t[2][0], q1.x, w0); fma2(t[3][0], q1.y, w0);
            fma2(t[4][0], q2.x, w0); fma2(t[5][0], q2.y, w0); fma2(t[6][0], q3.x, w0); fma2(t[7][0], q3.y, w0);
            fma2(t[0][1], q0.x, w1); fma2(t[1][1], q0.y, w1); fma2(t[2][1], q1.x, w1); fma2(t[3][1], q1.y, w1);
            fma2(t[4][1], q2.x, w1); fma2(t[5][1], q2.y, w1); fma2(t[6][1], q3.x, w1); fma2(t[7][1], q3.y, w1);
            fma2(t[0][2], q0.x, w2); fma2(t[1][2], q0.y, w2); fma2(t[2][2], q1.x, w2); fma2(t[3][2], q1.y, w2);
            fma2(t[4][2], q2.x, w2); fma2(t[5][2], q2.y, w2); fma2(t[6][2], q3.x, w2); fma2(t[7][2], q3.y, w2);
            fma2(t[0][3], q0.x, w3); fma2(t[1][3], q0.y, w3); fma2(t[2][3], q1.x, w3); fma2(t[3][3], q1.y, w3);
            fma2(t[4][3], q2.x, w3); fma2(t[5][3], q2.y, w3); fma2(t[6][3], q3.x, w3); fma2(t[7][3], q3.y, w3);
          }
        }
        // t row (primal only; tangent of t is zero)
        {
          const u64 tsp = pk2(ts, ts);
          const u64* wr = W0d + 16*HID + c0;
          fma2(pacc[0], tsp, wr[0]);  fma2(pacc[1], tsp, wr[32]);
          fma2(pacc[2], tsp, wr[64]); fma2(pacc[3], tsp, wr[96]);
        }
        __syncwarp();
        act_store(ws, pacc, t, c0);
        __syncwarp();
      }

      // ================= hidden layers 1..3 =================
      hidden_layer(ws, W1d, b1, c0);
      hidden_layer(ws, W2d, b2, c0);
      hidden_layer(ws, W3d, b3, c0);

      // ================= output layer (W4), split-k across half-warps ==========
      {
        u64 o[8]; u64 pa = 0ULL;
        #pragma unroll
        for (int rp = 0; rp < 8; ++rp) o[rp] = 0ULL;
        #pragma unroll 1
        for (int ki = 0; ki < 64; ++ki) {
          int k = k0 + ki;
          const ulonglong2* row = reinterpret_cast<const ulonglong2*>(&ws->dHT[k][0]);
          ulonglong2 q0 = row[0], q1 = row[1], q2 = row[2], q3 = row[3];
          u64 hjs = ws->hJS[k];
          u64 w = W4d[k*DIM + d];
          fma2(pa, hjs, w);
          fma2(o[0], q0.x, w); fma2(o[1], q0.y, w);
          fma2(o[2], q1.x, w); fma2(o[3], q1.y, w);
          fma2(o[4], q2.x, w); fma2(o[5], q2.y, w);
          fma2(o[6], q3.x, w); fma2(o[7], q3.y, w);
        }
        // combine halves via shuffle (both halves end with identical totals)
        #pragma unroll
        for (int rp = 0; rp < 8; ++rp) {
          float a, b; upk2(o[rp], a, b);
          a += __shfl_xor_sync(0xffffffffu, a, 16);
          b += __shfl_xor_sync(0xffffffffu, b, 16);
          u2[rp] = pk2(a, b);
        }
        {
          float a, b; upk2(pa, a, b);
          a += __shfl_xor_sync(0xffffffffu, a, 16);
          b += __shfl_xor_sync(0xffffffffu, b, 16);
          float bb = b4[d];
          kst2 = pk2(a + bb, b + bb);
        }
        #pragma unroll
        for (int rp = 0; rp < 8; ++rp) fma2(usum2[rp], u2[rp], wgtp);
        fma2(ksum2, kst2, wgtp);
      }
    } // stages

    // RK4 update
    #pragma unroll
    for (int rp = 0; rp < 8; ++rp) fma2(v2[rp], usum2[rp], fp);
    fma2(z2, ksum2, fp);
  } // steps

  // ---- write results ----
  if (lane < 16) {
    float zl, zs_; upk2(z2, zl, zs_);
    g_y [p*DIM + d] = zl;
    g_ys[p*DIM + d] = zs_;
    #pragma unroll
    for (int rp = 0; rp < 8; ++rp) {
      float a, b; upk2(v2[rp], a, b);
      g_V[p*256 + (2*rp  )*16 + d] = a;   // [dir][comp]
      g_V[p*256 + (2*rp+1)*16 + d] = b;
    }
  }
}

// =========================== finalize (unchanged, verified) ===========================
__global__ void finalize_kernel(float* __restrict__ out)
{
  int p = blockIdx.x * blockDim.x + threadIdx.x;
  if (p >= NB) return;

  float gph[16]; float n2 = 0.f;
  #pragma unroll
  for (int i = 0; i < 16; ++i) {
    float dd = g_y[p*DIM + i] - g_ys[p*DIM + i];
    gph[i] = dd; n2 += dd * dd;
  }
  float inv = 1.f / (sqrtf(n2) + 1e-8f);
  #pragma unroll
  for (int i = 0; i < 16; ++i) gph[i] *= inv;

  float Vr[16][16];
  const float* V = g_V + p * 256;
  for (int j = 0; j < 16; ++j)
    for (int i = 0; i < 16; ++i) Vr[j][i] = V[j*16 + i];

  float gx[16];
  for (int j = 0; j < 16; ++j) {
    float sacc = 0.f;
    for (int i = 0; i < 16; ++i) sacc += Vr[j][i] * gph[i];
    gx[j] = sacc;
  }

  float G[16][16];
  for (int j = 0; j < 16; ++j)
    for (int k = 0; k <= j; ++k) {
      float sacc = 0.f;
      for (int i = 0; i < 16; ++i) sacc += Vr[j][i] * Vr[k][i];
      G[j][k] = sacc; G[k][j] = sacc;
    }
  for (int j = 0; j < 16; ++j) G[j][j] += 1e-6f;

  for (int j = 0; j < 16; ++j) {
    float dd = G[j][j];
    for (int k = 0; k < j; ++k) dd -= G[j][k] * G[j][k];
    dd = sqrtf(fmaxf(dd, 1e-30f));
    G[j][j] = dd;
    float id = 1.f / dd;
    for (int i = j + 1; i < 16; ++i) {
      float sacc = G[i][j];
      for (int k = 0; k < j; ++k) sacc -= G[i][k] * G[j][k];
      G[i][j] = sacc * id;
    }
  }
  float yv[16];
  for (int i = 0; i < 16; ++i) {
    float sacc = gx[i];
    for (int k = 0; k < i; ++k) sacc -= G[i][k] * yv[k];
    yv[i] = sacc / G[i][i];
  }
  float sol[16];
  for (int i = 15; i >= 0; --i) {
    float sacc = yv[i];
    for (int k = i + 1; k < 16; ++k) sacc -= G[k][i] * sol[k];
    sol[i] = sacc / G[i][i];
  }
  for (int j = 0; j < 16; ++j) out[p*DIM + j] = -sol[j];
}

extern "C" void kernel_launch(void* const* d_in, const int* in_sizes, int n_in,
                              void* d_out, int out_size)
{
  const float* x  = (const float*)d_in[0];
  const float* xs = (const float*)d_in[1];
  const float* W0 = (const float*)d_in[2];
  const float* b0 = (const float*)d_in[3];
  const float* W1 = (const float*)d_in[4];
  const float* b1 = (const float*)d_in[5];
  const float* W2 = (const float*)d_in[6];
  const float* b2 = (const float*)d_in[7];
  const float* W3 = (const float*)d_in[8];
  const float* b3 = (const float*)d_in[9];
  const float* W4 = (const float*)d_in[10];
  const float* b4 = (const float*)d_in[11];
  float* out = (float*)d_out;

  dup_w_kernel<<<64, 256>>>(W0, W1, W2, W3, W4);

  size_t sh = sizeof(WS) * 8;   // 12672 * 8 = 101376 bytes
  cudaFuncSetAttribute(flow_jac_kernel, cudaFuncAttributeMaxDynamicSharedMemorySize, (int)sh);
  flow_jac_kernel<<<128, 256, sh>>>(x, xs, b0, b1, b2, b3, b4);
  finalize_kernel<<<8, 128>>>(out);
}

// round 5
// speedup vs baseline: 1.0411x; 1.0411x over previous
#include <cuda_runtime.h>
#include <math.h>

#define NB      1024
#define HID     128
#define DIM     16
#define NSTEPS  10

// ---------------- device globals (no allocation allowed) ----------------
__device__ float g_y [NB*DIM];
__device__ float g_ys[NB*DIM];
__device__ float g_V [NB*DIM*DIM];   // g_V[p][dir j][comp i] = J[i][j]
__device__ float g_W4T[DIM*HID];     // W4 transposed: [d][k]

__global__ void prep_kernel(const float* __restrict__ W4)
{
  int i = blockIdx.x * blockDim.x + threadIdx.x;
  if (i < HID*DIM) {
    int k = i / DIM, d = i % DIM;
    g_W4T[d*HID + k] = W4[i];
  }
}

// ---------------- per-warp workspace ----------------
struct WS {
  float dH[8][HID];     // 8 tangent rows (this warp's dirs), 4096 B
  float hJ[HID];        // primal hidden, J point
  float hS[HID];        // primal hidden, star point
  float vin[8][16];     // stage tangent input [row][comp]
  float zinJ[16];
  float zinS[16];
};
// sizeof = (1024+128+128+128+16+16)*4 = 5760 bytes, 16B-aligned fields

__device__ __forceinline__ float4 ldf4(const float* p) {
  return *reinterpret_cast<const float4*>(p);
}
__device__ __forceinline__ void stf4(float* p, float4 v) {
  *reinterpret_cast<float4*>(p) = v;
}

// activation + scaled tangent store: lane owns cols c4..c4+3
__device__ __forceinline__ void act_store(WS* ws, float pJ[4], float pS[4],
                                          float t[8][4], int c4)
{
  float g[4], hj[4], hs[4];
  #pragma unroll
  for (int j = 0; j < 4; ++j) {
    hj[j] = tanhf(pJ[j]);
    hs[j] = tanhf(pS[j]);
    g[j]  = 1.f - hj[j]*hj[j];
  }
  stf4(&ws->hJ[c4], make_float4(hj[0], hj[1], hj[2], hj[3]));
  stf4(&ws->hS[c4], make_float4(hs[0], hs[1], hs[2], hs[3]));
  #pragma unroll
  for (int r = 0; r < 8; ++r)
    stf4(&ws->dH[r][c4],
         make_float4(g[0]*t[r][0], g[1]*t[r][1], g[2]*t[r][2], g[3]*t[r][3]));
}

// fused hidden layer: primal (J,S) + 8 tangent rows; K = 128
__device__ __forceinline__ void hidden_layer(WS* ws, const float* __restrict__ W,
                                             const float* __restrict__ b, int c4)
{
  float t[8][4];
  #pragma unroll
  for (int r = 0; r < 8; ++r)
    #pragma unroll
    for (int j = 0; j < 4; ++j) t[r][j] = 0.f;
  float4 bb = ldf4(&b[c4]);
  float pJ[4] = {bb.x, bb.y, bb.z, bb.w};
  float pS[4] = {bb.x, bb.y, bb.z, bb.w};

  #pragma unroll 1
  for (int kg = 0; kg < 32; ++kg) {
    int kb = kg * 4;
    float4 w[4];
    #pragma unroll
    for (int kk = 0; kk < 4; ++kk) w[kk] = ldf4(&W[(kb+kk)*HID + c4]);
    float4 hj = ldf4(&ws->hJ[kb]);
    float4 hs = ldf4(&ws->hS[kb]);
    const float hjv[4] = {hj.x, hj.y, hj.z, hj.w};
    const float hsv[4] = {hs.x, hs.y, hs.z, hs.w};
    #pragma unroll
    for (int kk = 0; kk < 4; ++kk) {
      pJ[0] += hjv[kk]*w[kk].x; pJ[1] += hjv[kk]*w[kk].y;
      pJ[2] += hjv[kk]*w[kk].z; pJ[3] += hjv[kk]*w[kk].w;
      pS[0] += hsv[kk]*w[kk].x; pS[1] += hsv[kk]*w[kk].y;
      pS[2] += hsv[kk]*w[kk].z; pS[3] += hsv[kk]*w[kk].w;
    }
    #pragma unroll
    for (int r = 0; r < 8; ++r) {
      float4 dd = ldf4(&ws->dH[r][kb]);
      t[r][0] += dd.x*w[0].x + dd.y*w[1].x + dd.z*w[2].x + dd.w*w[3].x;
      t[r][1] += dd.x*w[0].y + dd.y*w[1].y + dd.z*w[2].y + dd.w*w[3].y;
      t[r][2] += dd.x*w[0].z + dd.y*w[1].z + dd.z*w[2].z + dd.w*w[3].z;
      t[r][3] += dd.x*w[0].w + dd.y*w[1].w + dd.z*w[2].w + dd.w*w[3].w;
    }
  }
  __syncwarp();
  act_store(ws, pJ, pS, t, c4);
  __syncwarp();
}

__global__ __launch_bounds__(128, 3)
void flow_jac_kernel(const float* __restrict__ x,  const float* __restrict__ xs,
                     const float* __restrict__ W0, const float* __restrict__ b0,
                     const float* __restrict__ W1, const float* __restrict__ b1,
                     const float* __restrict__ W2, const float* __restrict__ b2,
                     const float* __restrict__ W3, const float* __restrict__ b3,
                     const float* __restrict__ b4)
{
  extern __shared__ unsigned char smem_raw[];
  const int warp = threadIdx.x >> 5;
  const int lane = threadIdx.x & 31;
  WS* ws = reinterpret_cast<WS*>(smem_raw) + warp;

  const int p  = blockIdx.x * 2 + (warp >> 1);   // 512 blocks * 2 points
  const int hf = warp & 1;                       // dir half: rows = 8*hf + 0..7
  const int c4 = lane * 4;                       // this lane's 4 hidden cols
  const int dlane = lane & 15;                   // owned component
  const int r0 = (lane >> 4) * 4;                // local tangent rows r0..r0+3
  const bool isJ = (lane < 16);

  // persistent register state
  float z = isJ ? x[p*DIM + dlane] : xs[p*DIM + dlane];  // own trajectory comp
  float v[4], u[4], kst = 0.f;
  #pragma unroll
  for (int rr = 0; rr < 4; ++rr) {
    v[rr] = ((8*hf + r0 + rr) == dlane) ? 1.f : 0.f;
    u[rr] = 0.f;
  }

  const float dt = 1.f / NSTEPS;
  const float f6 = dt / 6.f;
  const float b4d = b4[dlane];

  for (int step = 0; step < NSTEPS; ++step) {
    const float t0 = step * dt;
    float ksum = 0.f, usum[4] = {0.f, 0.f, 0.f, 0.f};

    for (int s = 0; s < 4; ++s) {
      const float cs  = (s == 0) ? 0.f : ((s == 3) ? dt : 0.5f * dt);
      const float ts  = t0 + cs;
      const float wgt = (s == 0 || s == 3) ? 1.f : 2.f;

      // ---- stage inputs ----
      float zin = z + cs * kst;
      if (isJ) ws->zinJ[dlane] = zin; else ws->zinS[dlane] = zin;
      #pragma unroll
      for (int rr = 0; rr < 4; ++rr)
        ws->vin[r0 + rr][dlane] = v[rr] + cs * u[rr];
      __syncwarp();

      // ================= layer 0 (K=16 + t row), fused primal+tangent ========
      {
        float t[8][4];
        #pragma unroll
        for (int r = 0; r < 8; ++r)
          #pragma unroll
          for (int j = 0; j < 4; ++j) t[r][j] = 0.f;
        float4 bb = ldf4(&b0[c4]);
        float pJ[4] = {bb.x, bb.y, bb.z, bb.w};
        float pS[4] = {bb.x, bb.y, bb.z, bb.w};

        #pragma unroll
        for (int kg = 0; kg < 4; ++kg) {
          int kb = kg * 4;
          float4 w[4];
          #pragma unroll
          for (int kk = 0; kk < 4; ++kk) w[kk] = ldf4(&W0[(kb+kk)*HID + c4]);
          float4 zj = ldf4(&ws->zinJ[kb]);
          float4 zs4 = ldf4(&ws->zinS[kb]);
          const float zjv[4] = {zj.x, zj.y, zj.z, zj.w};
          const float zsv[4] = {zs4.x, zs4.y, zs4.z, zs4.w};
          #pragma unroll
          for (int kk = 0; kk < 4; ++kk) {
            pJ[0] += zjv[kk]*w[kk].x; pJ[1] += zjv[kk]*w[kk].y;
            pJ[2] += zjv[kk]*w[kk].z; pJ[3] += zjv[kk]*w[kk].w;
            pS[0] += zsv[kk]*w[kk].x; pS[1] += zsv[kk]*w[kk].y;
            pS[2] += zsv[kk]*w[kk].z; pS[3] += zsv[kk]*w[kk].w;
          }
          #pragma unroll
          for (int r = 0; r < 8; ++r) {
            float4 dd = ldf4(&ws->vin[r][kb]);
            t[r][0] += dd.x*w[0].x + dd.y*w[1].x + dd.z*w[2].x + dd.w*w[3].x;
            t[r][1] += dd.x*w[0].y + dd.y*w[1].y + dd.z*w[2].y + dd.w*w[3].y;
            t[r][2] += dd.x*w[0].z + dd.y*w[1].z + dd.z*w[2].z + dd.w*w[3].z;
            t[r][3] += dd.x*w[0].w + dd.y*w[1].w + dd.z*w[2].w + dd.w*w[3].w;
          }
        }
        // time row (primal only; tangent of t is zero)
        float4 wt = ldf4(&W0[16*HID + c4]);
        pJ[0] += ts*wt.x; pJ[1] += ts*wt.y; pJ[2] += ts*wt.z; pJ[3] += ts*wt.w;
        pS[0] += ts*wt.x; pS[1] += ts*wt.y; pS[2] += ts*wt.z; pS[3] += ts*wt.w;

        __syncwarp();   // all lanes done reading hJ/hS/dH of previous stage
        act_store(ws, pJ, pS, t, c4);
        __syncwarp();
      }

      // ================= hidden layers 1..3 =================
      hidden_layer(ws, W1, b1, c4);
      hidden_layer(ws, W2, b2, c4);
      hidden_layer(ws, W3, b3, c4);

      // ================= output layer (K=128 -> 16) =========================
      {
        float o[4] = {0.f, 0.f, 0.f, 0.f};
        float pa = 0.f;
        const float* hb = isJ ? ws->hJ : ws->hS;
        const float* w4row = g_W4T + dlane*HID;
        #pragma unroll 1
        for (int kg = 0; kg < 32; ++kg) {
          int kb = kg * 4;
          float4 h4 = ldf4(&hb[kb]);
          float4 w4 = ldf4(&w4row[kb]);
          pa += h4.x*w4.x + h4.y*w4.y + h4.z*w4.z + h4.w*w4.w;
          #pragma unroll
          for (int rr = 0; rr < 4; ++rr) {
            float4 dd = ldf4(&ws->dH[r0+rr][kb]);
            o[rr] += dd.x*w4.x + dd.y*w4.y + dd.z*w4.z + dd.w*w4.w;
          }
        }
        kst = pa + b4d;
        ksum += wgt * kst;
        #pragma unroll
        for (int rr = 0; rr < 4; ++rr) {
          u[rr] = o[rr];
          usum[rr] += wgt * o[rr];
        }
      }
    } // stages

    // RK4 update
    z += f6 * ksum;
    #pragma unroll
    for (int rr = 0; rr < 4; ++rr) v[rr] += f6 * usum[rr];
  } // steps

  // ---- write results ----
  if (isJ) g_y [p*DIM + dlane] = z;
  else     g_ys[p*DIM + dlane] = z;
  #pragma unroll
  for (int rr = 0; rr < 4; ++rr)
    g_V[p*256 + (8*hf + r0 + rr)*16 + dlane] = v[rr];
}

// =========================== finalize (unchanged, verified) ===========================
__global__ void finalize_kernel(float* __restrict__ out)
{
  int p = blockIdx.x * blockDim.x + threadIdx.x;
  if (p >= NB) return;

  float gph[16]; float n2 = 0.f;
  #pragma unroll
  for (int i = 0; i < 16; ++i) {
    float dd = g_y[p*DIM + i] - g_ys[p*DIM + i];
    gph[i] = dd; n2 += dd * dd;
  }
  float inv = 1.f / (sqrtf(n2) + 1e-8f);
  #pragma unroll
  for (int i = 0; i < 16; ++i) gph[i] *= inv;

  float Vr[16][16];
  const float* V = g_V + p * 256;
  for (int j = 0; j < 16; ++j)
    for (int i = 0; i < 16; ++i) Vr[j][i] = V[j*16 + i];

  float gx[16];
  for (int j = 0; j < 16; ++j) {
    float sacc = 0.f;
    for (int i = 0; i < 16; ++i) sacc += Vr[j][i] * gph[i];
    gx[j] = sacc;
  }

  float G[16][16];
  for (int j = 0; j < 16; ++j)
    for (int k = 0; k <= j; ++k) {
      float sacc = 0.f;
      for (int i = 0; i < 16; ++i) sacc += Vr[j][i] * Vr[k][i];
      G[j][k] = sacc; G[k][j] = sacc;
    }
  for (int j = 0; j < 16; ++j) G[j][j] += 1e-6f;

  for (int j = 0; j < 16; ++j) {
    float dd = G[j][j];
    for (int k = 0; k < j; ++k) dd -= G[j][k] * G[j][k];
    dd = sqrtf(fmaxf(dd, 1e-30f));
    G[j][j] = dd;
    float id = 1.f / dd;
    for (int i = j + 1; i < 16; ++i) {
      float sacc = G[i][j];
      for (int k = 0; k < j; ++k) sacc -= G[i][k] * G[j][k];
      G[i][j] = sacc * id;
    }
  }
  float yv[16];
  for (int i = 0; i < 16; ++i) {
    float sacc = gx[i];
    for (int k = 0; k < i; ++k) sacc -= G[i][k] * yv[k];
    yv[i] = sacc / G[i][i];
  }
  float sol[16];
  for (int i = 15; i >= 0; --i) {
    float sacc = yv[i];
    for (int k = i + 1; k < 16; ++k) sacc -= G[k][i] * sol[k];
    sol[i] = sacc / G[i][i];
  }
  for (int j = 0; j < 16; ++j) out[p*DIM + j] = -sol[j];
}

extern "C" void kernel_launch(void* const* d_in, const int* in_sizes, int n_in,
                              void* d_out, int out_size)
{
  const float* x  = (const float*)d_in[0];
  const float* xs = (const float*)d_in[1];
  const float* W0 = (const float*)d_in[2];
  const float* b0 = (const float*)d_in[3];
  const float* W1 = (const float*)d_in[4];
  const float* b1 = (const float*)d_in[5];
  const float* W2 = (const float*)d_in[6];
  const float* b2 = (const float*)d_in[7];
  const float* W3 = (const float*)d_in[8];
  const float* b3 = (const float*)d_in[9];
  const float* W4 = (const float*)d_in[10];
  const float* b4 = (const float*)d_in[11];
  float* out = (float*)d_out;

  prep_kernel<<<8, 256>>>(W4);

  size_t sh = sizeof(WS) * 4;   // 5760 * 4 = 23040 bytes per CTA
  cudaFuncSetAttribute(flow_jac_kernel, cudaFuncAttributeMaxDynamicSharedMemorySize, (int)sh);
  flow_jac_kernel<<<512, 128, sh>>>(x, xs, W0, b0, W1, b1, W2, b2, W3, b3, b4);
  finalize_kernel<<<8, 128>>>(out);
}